// round 11
// baseline (speedup 1.0000x reference)
#include <cuda_runtime.h>
#include <cstdint>
#include <cstddef>

#define B_   32
#define T_   512
#define KIN  1024
#define H_   1024
#define G_   4096
#define M_   (B_*T_)
#define JT   4               // j-units per block
#define NBLK 256             // 2 blocks per SM target
#define NTHR 512             // 16 warps

__device__ float g_xproj[(size_t)M_ * G_];
__device__ float g_h[2][B_*H_];
__device__ unsigned g_arr[8*32];   // tree barrier, 8 slots 128 B apart

typedef unsigned long long u64;

__device__ __forceinline__ void fma2(u64 &d, u64 a, u64 b){
    asm("fma.rn.f32x2 %0, %1, %2, %0;" : "+l"(d) : "l"(a), "l"(b));
}
__device__ __forceinline__ u64 pack2(float lo, float hi){
    u64 r; asm("mov.b64 %0, {%1,%2};" : "=l"(r) : "f"(lo), "f"(hi)); return r;
}
__device__ __forceinline__ float2 unpack2(u64 v){
    float2 f; asm("mov.b64 {%0,%1}, %2;" : "=f"(f.x), "=f"(f.y) : "l"(v)); return f;
}

// grid sync; 256 blocks, 32 arrivals per slot per epoch
__device__ __forceinline__ void grid_sync(int jb, unsigned e)
{
    __syncthreads();
    if (threadIdx.x == 0) {
        __threadfence();
        atomicAdd(&g_arr[(jb & 7) * 32], 1u);
        unsigned tgt = 32u * e;
        volatile unsigned* a = g_arr;
        for (;;) {
            unsigned v0 = a[0*32], v1 = a[1*32], v2 = a[2*32], v3 = a[3*32];
            unsigned v4 = a[4*32], v5 = a[5*32], v6 = a[6*32], v7 = a[7*32];
            if (v0>=tgt && v1>=tgt && v2>=tgt && v3>=tgt &&
                v4>=tgt && v5>=tgt && v6>=tgt && v7>=tgt) break;
        }
        __threadfence();
    }
    __syncthreads();
}

// ---------------- scan smem layout (floats) ----------------
// hs half: 16 rows, k padded: off(k) = k + (k>>4)*4, pitch 1280.
#define HP          1280
#define HS_FLOATS   (16*HP)                  // 80 KB
#define PB_FLOATS   (16*16*16)               // [w][bl][c] 16 KB
#define SP_FLOATS   (16*33)
#define SMEM_BYTES  ((HS_FLOATS + PB_FLOATS + SP_FLOATS)*4)   // ~100.4 KB

// xproj aliases: As2 u64[16][66], then Bst float[16][132]
#define XP_BST_OFF  (16*66*2)                // float offset

extern __shared__ float smemf[];

__global__ void __launch_bounds__(NTHR, 2) lstm_fused(
    const float* __restrict__ A,
    const float* __restrict__ h0,
    const float* __restrict__ c0,
    const float* __restrict__ Wih,
    const float* __restrict__ bih,
    const float* __restrict__ Whh,
    const float* __restrict__ bhh,
    float* __restrict__ out)
{
    const int tid = threadIdx.x;
    const int jb  = blockIdx.x;

    if (jb == 0 && tid < 8) { g_arr[tid*32] = 0u; __threadfence(); }
    unsigned epoch = 0;

    // ==============================================================
    // Phase A: xproj. 64m x 128n tiles, BK=16; 32 tiles per block.
    // (proven round-6 512-thread geometry)
    // ==============================================================
    {
        u64*   As2 = (u64*)smemf;                 // [16][66]
        float* Bst = smemf + XP_BST_OFF;          // [16][132]

        const int tx = tid & 31;
        const int ty = tid >> 5;
        const int wrow = tid >> 2;                // 0..127
        const int wk   = (tid & 3) * 4;
        const int lrow = (tid & 255) >> 2;        // 0..63
        const int lk   = (tid & 3) * 4;

        for (int i6 = 0; i6 < 32; i6++) {
            int tt = jb*32 + i6;
            int m0 = (tt >> 5) * 64;
            int n0 = (tt & 31) * 128;

            u64 acc[4][2];
            #pragma unroll
            for (int i = 0; i < 4; i++) { acc[i][0]=0ULL; acc[i][1]=0ULL; }

            const float* Arow = A   + (size_t)(m0 + lrow)*KIN + lk;
            const float* Wrow = Wih + (size_t)(n0 + wrow)*KIN + wk;

            for (int kc = 0; kc < KIN; kc += 16) {
                if (tid < 256) {
                    float4 av = *(const float4*)(Arow + kc);
                    As2[(lk+0)*66 + lrow] = pack2(av.x, av.x);
                    As2[(lk+1)*66 + lrow] = pack2(av.y, av.y);
                    As2[(lk+2)*66 + lrow] = pack2(av.z, av.z);
                    As2[(lk+3)*66 + lrow] = pack2(av.w, av.w);
                }
                float4 wv = *(const float4*)(Wrow + kc);
                Bst[(wk+0)*132 + wrow] = wv.x;
                Bst[(wk+1)*132 + wrow] = wv.y;
                Bst[(wk+2)*132 + wrow] = wv.z;
                Bst[(wk+3)*132 + wrow] = wv.w;
                __syncthreads();

                #pragma unroll
                for (int k = 0; k < 16; k++) {
                    const ulonglong2* ap =
                        (const ulonglong2*)&As2[k*66 + ty*4];
                    ulonglong2 a01 = ap[0];
                    ulonglong2 a23 = ap[1];
                    u64 b0 = *(const u64*)&Bst[k*132 + tx*4];
                    u64 b1 = *(const u64*)&Bst[k*132 + tx*4 + 2];
                    fma2(acc[0][0], a01.x, b0); fma2(acc[0][1], a01.x, b1);
                    fma2(acc[1][0], a01.y, b0); fma2(acc[1][1], a01.y, b1);
                    fma2(acc[2][0], a23.x, b0); fma2(acc[2][1], a23.x, b1);
                    fma2(acc[3][0], a23.y, b0); fma2(acc[3][1], a23.y, b1);
                }
                __syncthreads();
            }

            float bn0 = bih[n0 + tx*4];
            float bn1 = bih[n0 + tx*4 + 1];
            float bn2 = bih[n0 + tx*4 + 2];
            float bn3 = bih[n0 + tx*4 + 3];
            #pragma unroll
            for (int i = 0; i < 4; i++) {
                int m = m0 + ty*4 + i;
                float* crow = g_xproj + (size_t)m*G_ + n0 + tx*4;
                float2 v0 = unpack2(acc[i][0]);
                float2 v1 = unpack2(acc[i][1]);
                crow[0] = v0.x + bn0;
                crow[1] = v0.y + bn1;
                crow[2] = v1.x + bn2;
                crow[3] = v1.y + bn3;
            }
        }
    }

    grid_sync(jb, ++epoch);

    // ==============================================================
    // Phase B: scan. Block owns 16 preact cols (4 gates x 4 j).
    // 16 warps; warp w = k-slice 64; lane = (ll: 8 col-pairs, kg: 4).
    // Thread: 2 cols x 16 k -> wA[8]+wB[8] = 32 regs.
    // hs single-buffered per b-half; dual co-resident blocks overlap.
    // ==============================================================
    float* hs   = smemf;                    // [16][HP]
    float* pbuf = smemf + HS_FLOATS;        // [16 w][16 bl][16 c]
    float* sp   = pbuf + PB_FLOATS;         // [16 c][33]

    const int w    = tid >> 5;              // 0..15
    const int lane = tid & 31;
    const int ll   = lane & 7;              // col pair
    const int kg   = lane >> 3;             // 0..3
    const int cc0  = 2*ll;                  // cols cc0, cc0+1
    const int ks   = w*64 + kg*16;          // k base
    const int ksp  = w*80 + kg*20;          // padded float offset

    const int n0c = (cc0>>2)*H_ + jb*JT + (cc0&3);
    const int n1c = ((cc0+1)>>2)*H_ + jb*JT + ((cc0+1)&3);

    u64 wA[8], wB[8];
    {
        const float4* pA = (const float4*)(Whh + (size_t)n0c*KIN + ks);
        const float4* pB = (const float4*)(Whh + (size_t)n1c*KIN + ks);
        #pragma unroll
        for (int m = 0; m < 4; m++) {
            float4 a = pA[m], b = pB[m];
            wA[2*m] = pack2(a.x, a.y); wA[2*m+1] = pack2(a.z, a.w);
            wB[2*m] = pack2(b.x, b.y); wB[2*m+1] = pack2(b.z, b.w);
        }
    }

    const bool upd = (tid < 128);
    const int ub = tid >> 2;                // 0..31 (tid<128)
    const int uj = tid & 3;
    const int jg = jb*JT + uj;
    float cstate = 0.f;
    if (upd) cstate = c0[ub*H_ + jg];

    const size_t OFF_H = (size_t)B_*T_*H_;
    const size_t OFF_C = OFF_H + (size_t)B_*H_;

    for (int t = 0; t < T_; t++) {
        const float* hprev = (t == 0) ? h0 : g_h[t & 1];
        float*       hnext = g_h[(t + 1) & 1];
        const float4* hsrc = (const float4*)hprev;

        // prefetch xproj + bhh
        float xp0=0,xp1=0,xp2=0,xp3=0, bh0=0,bh1=0,bh2=0,bh3=0;
        if (upd) {
            const float* xrow = g_xproj + ((size_t)ub*T_ + t)*G_ + jg;
            xp0 = xrow[0]; xp1 = xrow[H_]; xp2 = xrow[2*H_]; xp3 = xrow[3*H_];
            bh0 = bhh[jg]; bh1 = bhh[H_+jg];
            bh2 = bhh[2*H_+jg]; bh3 = bhh[3*H_+jg];
        }

        // stage half 0 (global b rows 0..15): 4096 float4
        #pragma unroll
        for (int it = 0; it < 8; it++) {
            int e = tid + NTHR*it;
            int lr = e >> 8, c4 = e & 255;
            *(float4*)(hs + lr*HP + c4*4 + (c4>>2)*4) = hsrc[lr*256 + c4];
        }
        __syncthreads();                     // hs half0 ready

        // main0: b rows 0..15
        #pragma unroll 4
        for (int bl = 0; bl < 16; bl++) {
            const ulonglong2* hb = (const ulonglong2*)(hs + bl*HP + ksp);
            u64 a0 = 0ULL, a1 = 0ULL;
            #pragma unroll
            for (int m = 0; m < 4; m++) {
                ulonglong2 hv = hb[m];
                fma2(a0, wA[2*m],   hv.x); fma2(a0, wA[2*m+1], hv.y);
                fma2(a1, wB[2*m],   hv.x); fma2(a1, wB[2*m+1], hv.y);
            }
            float2 f0 = unpack2(a0), f1 = unpack2(a1);
            float p0 = f0.x + f0.y;
            float p1 = f1.x + f1.y;
            p0 += __shfl_xor_sync(0xffffffffu, p0, 8);
            p1 += __shfl_xor_sync(0xffffffffu, p1, 8);
            p0 += __shfl_xor_sync(0xffffffffu, p0, 16);
            p1 += __shfl_xor_sync(0xffffffffu, p1, 16);
            if (lane < 8) {
                float2 st; st.x = p0; st.y = p1;
                *(float2*)&pbuf[(w*16 + bl)*16 + cc0] = st;
            }
        }
        __syncthreads();                     // pbuf0 done, hs reusable

        // stage half 1 (overwrites hs) + reduce0 in parallel
        #pragma unroll
        for (int it = 0; it < 8; it++) {
            int e = tid + NTHR*it;
            int lr = e >> 8, c4 = e & 255;
            *(float4*)(hs + lr*HP + c4*4 + (c4>>2)*4) =
                hsrc[(16 + lr)*256 + c4];
        }
        if (tid < 256) {
            int cc = tid & 15, bl = tid >> 4;
            float s = 0.f;
            #pragma unroll
            for (int ww = 0; ww < 16; ww++)
                s += pbuf[(ww*16 + bl)*16 + cc];
            sp[cc*33 + bl] = s;
        }
        __syncthreads();                     // hs half1 + sp0 ready

        // update half0 (tid<64, ub 0..15) then main1
        if (tid < 64) {
            float p0 = sp[(0*4+uj)*33 + ub] + xp0 + bh0;
            float p1 = sp[(1*4+uj)*33 + ub] + xp1 + bh1;
            float p2 = sp[(2*4+uj)*33 + ub] + xp2 + bh2;
            float p3 = sp[(3*4+uj)*33 + ub] + xp3 + bh3;
            float ig = 1.f/(1.f+__expf(-p0));
            float fg = 1.f/(1.f+__expf(-p1));
            float og = 1.f/(1.f+__expf(-p2));
            float gg = tanhf(p3);
            float cn = cstate*fg + ig*gg;
            cstate = cn;
            float hn = og * tanhf(cn);
            hnext[ub*H_ + jg] = hn;
            out[((size_t)ub*T_ + t)*H_ + jg] = hn;
            if (t == T_-1) {
                out[OFF_H + (size_t)ub*H_ + jg] = hn;
                out[OFF_C + (size_t)ub*H_ + jg] = cn;
            }
        }

        // main1: b rows 16..31 (local hs rows 0..15)
        #pragma unroll 4
        for (int bl = 0; bl < 16; bl++) {
            const ulonglong2* hb = (const ulonglong2*)(hs + bl*HP + ksp);
            u64 a0 = 0ULL, a1 = 0ULL;
            #pragma unroll
            for (int m = 0; m < 4; m++) {
                ulonglong2 hv = hb[m];
                fma2(a0, wA[2*m],   hv.x); fma2(a0, wA[2*m+1], hv.y);
                fma2(a1, wB[2*m],   hv.x); fma2(a1, wB[2*m+1], hv.y);
            }
            float2 f0 = unpack2(a0), f1 = unpack2(a1);
            float p0 = f0.x + f0.y;
            float p1 = f1.x + f1.y;
            p0 += __shfl_xor_sync(0xffffffffu, p0, 8);
            p1 += __shfl_xor_sync(0xffffffffu, p1, 8);
            p0 += __shfl_xor_sync(0xffffffffu, p0, 16);
            p1 += __shfl_xor_sync(0xffffffffu, p1, 16);
            if (lane < 8) {
                float2 st; st.x = p0; st.y = p1;
                *(float2*)&pbuf[(w*16 + bl)*16 + cc0] = st;
            }
        }
        __syncthreads();                     // pbuf1 ready

        // reduce1
        if (tid < 256) {
            int cc = tid & 15, bl = tid >> 4;
            float s = 0.f;
            #pragma unroll
            for (int ww = 0; ww < 16; ww++)
                s += pbuf[(ww*16 + bl)*16 + cc];
            sp[cc*33 + bl] = s;              // bl is local (b = 16+bl)
        }
        __syncthreads();                     // sp1 ready

        // update half1 (tid 64..127, ub 16..31; sp indexed by ub-16)
        if (tid >= 64 && tid < 128) {
            int bloc = ub - 16;
            float p0 = sp[(0*4+uj)*33 + bloc] + xp0 + bh0;
            float p1 = sp[(1*4+uj)*33 + bloc] + xp1 + bh1;
            float p2 = sp[(2*4+uj)*33 + bloc] + xp2 + bh2;
            float p3 = sp[(3*4+uj)*33 + bloc] + xp3 + bh3;
            float ig = 1.f/(1.f+__expf(-p0));
            float fg = 1.f/(1.f+__expf(-p1));
            float og = 1.f/(1.f+__expf(-p2));
            float gg = tanhf(p3);
            float cn = cstate*fg + ig*gg;
            cstate = cn;
            float hn = og * tanhf(cn);
            hnext[ub*H_ + jg] = hn;
            out[((size_t)ub*T_ + t)*H_ + jg] = hn;
            if (t == T_-1) {
                out[OFF_H + (size_t)ub*H_ + jg] = hn;
                out[OFF_C + (size_t)ub*H_ + jg] = cn;
            }
        }

        if (t + 1 < T_) grid_sync(jb, ++epoch);
    }
}

extern "C" void kernel_launch(void* const* d_in, const int* in_sizes, int n_in,
                              void* d_out, int out_size)
{
    (void)in_sizes; (void)n_in; (void)out_size;
    const float* inputs = (const float*)d_in[0];
    const float* h0     = (const float*)d_in[1];
    const float* c0     = (const float*)d_in[2];
    const float* Wih    = (const float*)d_in[3];
    const float* bih    = (const float*)d_in[4];
    const float* Whh    = (const float*)d_in[5];
    const float* bhh    = (const float*)d_in[6];
    float* out = (float*)d_out;

    cudaFuncSetAttribute(lstm_fused,
                         cudaFuncAttributeMaxDynamicSharedMemorySize,
                         SMEM_BYTES);

    lstm_fused<<<NBLK, NTHR, SMEM_BYTES>>>(
        inputs, h0, c0, Wih, bih, Whh, bhh, out);
}

// round 13
// speedup vs baseline: 1.4043x; 1.4043x over previous
#include <cuda_runtime.h>
#include <cuda_bf16.h>
#include <cstdint>
#include <cstddef>

#define B_   32
#define T_   512
#define KIN  1024
#define H_   1024
#define G_   4096
#define M_   (B_*T_)
#define NBLK 128
#define NTHR 512

__device__ float    g_xproj[(size_t)M_ * G_];
__device__ unsigned g_hh[2][B_*512];     // h hi, bf16x2 per k-pair
__device__ unsigned g_hl[2][B_*512];     // h lo
__device__ unsigned g_arr[8*32];         // tree barrier

typedef unsigned long long u64;

__device__ __forceinline__ void fma2(u64 &d, u64 a, u64 b){
    asm("fma.rn.f32x2 %0, %1, %2, %0;" : "+l"(d) : "l"(a), "l"(b));
}
__device__ __forceinline__ u64 pack2(float lo, float hi){
    u64 r; asm("mov.b64 %0, {%1,%2};" : "=l"(r) : "f"(lo), "f"(hi)); return r;
}
__device__ __forceinline__ float2 unpack2(u64 v){
    float2 f; asm("mov.b64 {%0,%1}, %2;" : "=f"(f.x), "=f"(f.y) : "l"(v)); return f;
}
__device__ __forceinline__ uint32_t smem_to_u32(const void* p) {
    uint32_t a;
    asm("{ .reg .u64 t; cvta.to.shared.u64 t, %1; cvt.u32.u64 %0, t; }"
        : "=r"(a) : "l"(p));
    return a;
}
__device__ __forceinline__ void ldsm_x4(uint32_t* r, uint32_t addr){
    asm volatile("ldmatrix.sync.aligned.m8n8.x4.shared.b16 {%0,%1,%2,%3}, [%4];"
        : "=r"(r[0]),"=r"(r[1]),"=r"(r[2]),"=r"(r[3]) : "r"(addr));
}
__device__ __forceinline__ void ldsm_x2(uint32_t* r, uint32_t addr){
    asm volatile("ldmatrix.sync.aligned.m8n8.x2.shared.b16 {%0,%1}, [%2];"
        : "=r"(r[0]),"=r"(r[1]) : "r"(addr));
}
__device__ __forceinline__ void mma16816(float* c, const uint32_t* a,
                                         const uint32_t* b){
    asm volatile("mma.sync.aligned.m16n8k16.row.col.f32.bf16.bf16.f32 "
        "{%0,%1,%2,%3}, {%4,%5,%6,%7}, {%8,%9}, {%0,%1,%2,%3};"
        : "+f"(c[0]),"+f"(c[1]),"+f"(c[2]),"+f"(c[3])
        : "r"(a[0]),"r"(a[1]),"r"(a[2]),"r"(a[3]),"r"(b[0]),"r"(b[1]));
}

__device__ __forceinline__ void grid_sync(int jb, unsigned e)
{
    __syncthreads();
    if (threadIdx.x == 0) {
        __threadfence();
        atomicAdd(&g_arr[(jb & 7) * 32], 1u);
        unsigned tgt = 16u * e;
        volatile unsigned* a = g_arr;
        for (;;) {
            unsigned v0=a[0],v1=a[32],v2=a[64],v3=a[96];
            unsigned v4=a[128],v5=a[160],v6=a[192],v7=a[224];
            if (v0>=tgt&&v1>=tgt&&v2>=tgt&&v3>=tgt&&
                v4>=tgt&&v5>=tgt&&v6>=tgt&&v7>=tgt) break;
        }
        __threadfence();
    }
    __syncthreads();
}

// scan smem byte offsets (also aliased by xproj phase & W-setup)
#define HPITCH    1032                    // bf16 per h/W row (16B-stride pad)
#define OFF_HHI   0                       // [32][HPITCH] bf16
#define OFF_HLO   66048
#define OFF_PD    132096                  // [8 ks][32 m][36] float
#define OFF_SP    168960                  // [32 m][40] float
#define OFF_SXP   174080                  // [32 b][32 n] float
#define SMEM_BYTES (174080 + 4096)
#define XP_BST_OFF (16*66*2)              // xproj alias: float off of Bst

extern __shared__ __align__(16) char smemc[];

__global__ void __launch_bounds__(NTHR, 1) lstm_fused(
    const float* __restrict__ A,
    const float* __restrict__ h0,
    const float* __restrict__ c0,
    const float* __restrict__ Wih,
    const float* __restrict__ bih,
    const float* __restrict__ Whh,
    const float* __restrict__ bhh,
    float* __restrict__ out)
{
    const int tid  = threadIdx.x;
    const int jb   = blockIdx.x;
    const int wid  = tid >> 5;
    const int lane = tid & 31;

    if (jb == 0 && tid < 8) { g_arr[tid*32] = 0u; __threadfence(); }
    unsigned epoch = 0;

    // ===== Phase A: xproj (proven fp32 f32x2), 64m x 128n, 64/blk =====
    {
        float* smemf = (float*)smemc;
        u64*   As2 = (u64*)smemf;
        float* Bst = smemf + XP_BST_OFF;
        const int tx = tid & 31, ty = tid >> 5;
        const int wrow = tid >> 2, wk = (tid & 3) * 4;
        const int lrow = (tid & 255) >> 2, lk = (tid & 3) * 4;

        for (int i6 = 0; i6 < 64; i6++) {
            int tt = jb*64 + i6;
            int m0 = (tt >> 5) * 64, n0 = (tt & 31) * 128;
            u64 acc[4][2];
            #pragma unroll
            for (int i = 0; i < 4; i++) { acc[i][0]=0ULL; acc[i][1]=0ULL; }
            const float* Arow = A   + (size_t)(m0 + lrow)*KIN + lk;
            const float* Wrow = Wih + (size_t)(n0 + wrow)*KIN + wk;

            for (int kc = 0; kc < KIN; kc += 16) {
                if (tid < 256) {
                    float4 av = *(const float4*)(Arow + kc);
                    As2[(lk+0)*66 + lrow] = pack2(av.x, av.x);
                    As2[(lk+1)*66 + lrow] = pack2(av.y, av.y);
                    As2[(lk+2)*66 + lrow] = pack2(av.z, av.z);
                    As2[(lk+3)*66 + lrow] = pack2(av.w, av.w);
                }
                float4 wv = *(const float4*)(Wrow + kc);
                Bst[(wk+0)*132 + wrow] = wv.x;
                Bst[(wk+1)*132 + wrow] = wv.y;
                Bst[(wk+2)*132 + wrow] = wv.z;
                Bst[(wk+3)*132 + wrow] = wv.w;
                __syncthreads();
                #pragma unroll
                for (int k = 0; k < 16; k++) {
                    const ulonglong2* ap = (const ulonglong2*)&As2[k*66 + ty*4];
                    ulonglong2 a01 = ap[0], a23 = ap[1];
                    u64 b0 = *(const u64*)&Bst[k*132 + tx*4];
                    u64 b1 = *(const u64*)&Bst[k*132 + tx*4 + 2];
                    fma2(acc[0][0], a01.x, b0); fma2(acc[0][1], a01.x, b1);
                    fma2(acc[1][0], a01.y, b0); fma2(acc[1][1], a01.y, b1);
                    fma2(acc[2][0], a23.x, b0); fma2(acc[2][1], a23.x, b1);
                    fma2(acc[3][0], a23.y, b0); fma2(acc[3][1], a23.y, b1);
                }
                __syncthreads();
            }
            float bn0 = bih[n0+tx*4], bn1 = bih[n0+tx*4+1];
            float bn2 = bih[n0+tx*4+2], bn3 = bih[n0+tx*4+3];
            #pragma unroll
            for (int i = 0; i < 4; i++) {
                float* crow = g_xproj + (size_t)(m0+ty*4+i)*G_ + n0 + tx*4;
                float2 v0 = unpack2(acc[i][0]), v1 = unpack2(acc[i][1]);
                crow[0]=v0.x+bn0; crow[1]=v0.y+bn1;
                crow[2]=v1.x+bn2; crow[3]=v1.y+bn3;
            }
        }
    }
    grid_sync(jb, ++epoch);

    // ===== Setup: W -> bf16 hi/lo smem; h0 -> bf16 hi/lo global =====
    char* sm = smemc;
    const uint32_t smu = smem_to_u32(sm);
    __nv_bfloat16* sHhi = (__nv_bfloat16*)(sm + OFF_HHI);
    __nv_bfloat16* sHlo = (__nv_bfloat16*)(sm + OFF_HLO);
    float* pd  = (float*)(sm + OFF_PD);
    float* sp  = (float*)(sm + OFF_SP);
    float* sxp = (float*)(sm + OFF_SXP);

    for (int i = tid; i < 32*1024; i += NTHR) {
        int n = i >> 10, k = i & 1023;
        int wr = (n >> 3)*H_ + jb*8 + (n & 7);
        float v = Whh[(size_t)wr*KIN + k];
        __nv_bfloat16 hb = __float2bfloat16(v);
        sHhi[n*HPITCH + k] = hb;
        sHlo[n*HPITCH + k] = __float2bfloat16(v - __bfloat162float(hb));
    }
    if (tid < 128) {
        int u = jb*128 + tid;
        int b = u >> 9, kp = u & 511;
        float v0 = h0[b*KIN + 2*kp], v1 = h0[b*KIN + 2*kp + 1];
        __nv_bfloat16 a0 = __float2bfloat16(v0), a1 = __float2bfloat16(v1);
        __nv_bfloat162 hp; hp.x = a0; hp.y = a1;
        __nv_bfloat162 lp;
        lp.x = __float2bfloat16(v0 - __bfloat162float(a0));
        lp.y = __float2bfloat16(v1 - __bfloat162float(a1));
        g_hh[0][u] = *(unsigned*)&hp;
        g_hl[0][u] = *(unsigned*)&lp;
    }
    __syncthreads();

    // A-fragments (W) into registers: warp = (mt, ks); 8 ktiles x hi/lo
    const int mt = wid & 1, ks = wid >> 1;
    uint32_t aHi[8][4], aLo[8][4];
    {
        int g = lane >> 3, r = lane & 7;
        int row = mt*16 + r + (g & 1)*8;
        int kof = (g >> 1)*8;
        #pragma unroll
        for (int kt = 0; kt < 8; kt++) {
            uint32_t boff = (uint32_t)(row*HPITCH + ks*128 + kt*16 + kof)*2;
            ldsm_x4(aHi[kt], smu + OFF_HHI + boff);
            ldsm_x4(aLo[kt], smu + OFF_HLO + boff);
        }
    }
    __syncthreads();
    grid_sync(jb, ++epoch);   // h0 conversion visible everywhere

    const int ub = tid >> 2, jjp = tid & 3;
    const int j0 = jb*8 + 2*jjp;
    float cs0 = 0.f, cs1 = 0.f;
    if (tid < 128) { cs0 = c0[ub*H_ + j0]; cs1 = c0[ub*H_ + j0 + 1]; }

    const int bl_r = lane & 7;
    const int bl_k = (lane >> 3) & 1;
    const size_t OFF_H = (size_t)B_*T_*H_;
    const size_t OFF_C = OFF_H + (size_t)B_*H_;

    // ===== Scan =====
    for (int t = 0; t < T_; t++) {
        // stage h (bf16 hi/lo) + sxp
        {
            const uint4* ph = (const uint4*)g_hh[t & 1];
            const uint4* pl = (const uint4*)g_hl[t & 1];
            #pragma unroll
            for (int it = 0; it < 8; it++) {
                int e = tid + NTHR*it;          // 0..4095
                int b = e >> 7, kq = e & 127;
                *(uint4*)(sm + OFF_HHI + (b*HPITCH + kq*8)*2) = ph[e];
                *(uint4*)(sm + OFF_HLO + (b*HPITCH + kq*8)*2) = pl[e];
            }
            #pragma unroll
            for (int v = tid; v < 1024; v += NTHR) {
                int b = v >> 5, n = v & 31;
                int col = (n >> 3)*H_ + jb*8 + (n & 7);
                sxp[v] = g_xproj[((size_t)b*T_ + t)*G_ + col] + bhh[col];
            }
        }
        __syncthreads();

        // MMA: acc[bt] over 8 ktiles x 3 splits
        {
            float acc[4][4];
            #pragma unroll
            for (int i = 0; i < 4; i++)
                acc[i][0]=acc[i][1]=acc[i][2]=acc[i][3]=0.f;
            #pragma unroll
            for (int kt = 0; kt < 8; kt++) {
                uint32_t k0 = (uint32_t)(ks*128 + kt*16 + bl_k*8);
                #pragma unroll
                for (int bt = 0; bt < 4; bt++) {
                    uint32_t bo = ((uint32_t)(bt*8 + bl_r)*HPITCH + k0)*2;
                    uint32_t bhi[2], blo[2];
                    ldsm_x2(bhi, smu + OFF_HHI + bo);
                    ldsm_x2(blo, smu + OFF_HLO + bo);
                    mma16816(acc[bt], aHi[kt], bhi);
                    mma16816(acc[bt], aHi[kt], blo);
                    mma16816(acc[bt], aLo[kt], bhi);
                }
            }
            int row = mt*16 + (lane >> 2);
            int bc  = (lane & 3)*2;
            #pragma unroll
            for (int bt = 0; bt < 4; bt++) {
                float* p0 = pd + (ks*32 + row)*36 + bt*8 + bc;
                p0[0] = acc[bt][0]; p0[1] = acc[bt][1];
                float* p1 = pd + (ks*32 + row + 8)*36 + bt*8 + bc;
                p1[0] = acc[bt][2]; p1[1] = acc[bt][3];
            }
        }
        __syncthreads();

        // reduce 8 k-split partials
        if (tid < 256) {
            int m = tid >> 3, q = tid & 7;
            float4 s = *(const float4*)(pd + m*36 + q*4);
            #pragma unroll
            for (int s8 = 1; s8 < 8; s8++) {
                float4 v = *(const float4*)(pd + (s8*32 + m)*36 + q*4);
                s.x += v.x; s.y += v.y; s.z += v.z; s.w += v.w;
            }
            *(float4*)(sp + m*40 + q*4) = s;
        }
        __syncthreads();

        // epilogue: thread (ub, jjp) owns cols j0, j0+1
        if (tid < 128) {
            float pre0[4], pre1[4];
            #pragma unroll
            for (int g = 0; g < 4; g++) {
                int n0 = g*8 + 2*jjp;
                pre0[g] = sp[n0*40 + ub]     + sxp[ub*32 + n0];
                pre1[g] = sp[(n0+1)*40 + ub] + sxp[ub*32 + n0 + 1];
            }
            float i0 = 1.f/(1.f+__expf(-pre0[0]));
            float f0 = 1.f/(1.f+__expf(-pre0[1]));
            float o0 = 1.f/(1.f+__expf(-pre0[2]));
            float q0 = tanhf(pre0[3]);
            float i1 = 1.f/(1.f+__expf(-pre1[0]));
            float f1 = 1.f/(1.f+__expf(-pre1[1]));
            float o1 = 1.f/(1.f+__expf(-pre1[2]));
            float q1 = tanhf(pre1[3]);
            cs0 = cs0*f0 + i0*q0;
            cs1 = cs1*f1 + i1*q1;
            float hn0 = o0 * tanhf(cs0);
            float hn1 = o1 * tanhf(cs1);

            out[((size_t)ub*T_ + t)*H_ + j0]     = hn0;
            out[((size_t)ub*T_ + t)*H_ + j0 + 1] = hn1;
            if (t == T_ - 1) {
                out[OFF_H + (size_t)ub*H_ + j0]     = hn0;
                out[OFF_H + (size_t)ub*H_ + j0 + 1] = hn1;
                out[OFF_C + (size_t)ub*H_ + j0]     = cs0;
                out[OFF_C + (size_t)ub*H_ + j0 + 1] = cs1;
            }
            __nv_bfloat16 a0 = __float2bfloat16(hn0);
            __nv_bfloat16 a1 = __float2bfloat16(hn1);
            __nv_bfloat162 hp; hp.x = a0; hp.y = a1;
            __nv_bfloat162 lp;
            lp.x = __float2bfloat16(hn0 - __bfloat162float(a0));
            lp.y = __float2bfloat16(hn1 - __bfloat162float(a1));
            g_hh[(t+1)&1][ub*512 + jb*4 + jjp] = *(unsigned*)&hp;
            g_hl[(t+1)&1][ub*512 + jb*4 + jjp] = *(unsigned*)&lp;
        }

        if (t + 1 < T_) grid_sync(jb, ++epoch);
    }
}

extern "C" void kernel_launch(void* const* d_in, const int* in_sizes, int n_in,
                              void* d_out, int out_size)
{
    (void)in_sizes; (void)n_in; (void)out_size;
    const float* inputs = (const float*)d_in[0];
    const float* h0     = (const float*)d_in[1];
    const float* c0     = (const float*)d_in[2];
    const float* Wih    = (const float*)d_in[3];
    const float* bih    = (const float*)d_in[4];
    const float* Whh    = (const float*)d_in[5];
    const float* bhh    = (const float*)d_in[6];
    float* out = (float*)d_out;

    cudaFuncSetAttribute(lstm_fused,
                         cudaFuncAttributeMaxDynamicSharedMemorySize,
                         SMEM_BYTES);

    lstm_fused<<<NBLK, NTHR, SMEM_BYTES>>>(
        inputs, h0, c0, Wih, bih, Whh, bhh, out);
}

// round 14
// speedup vs baseline: 1.7561x; 1.2505x over previous
#include <cuda_runtime.h>
#include <cuda_bf16.h>
#include <cstdint>
#include <cstddef>

#define B_   32
#define T_   512
#define KIN  1024
#define H_   1024
#define G_   4096
#define M_   (B_*T_)
#define NBLK 128
#define NTHR 1024

__device__ float    g_xproj[(size_t)M_ * G_];
__device__ unsigned g_hh[2][B_*512];     // h hi, bf16x2 per k-pair
__device__ unsigned g_hl[2][B_*512];     // h lo
__device__ unsigned g_arr[8*32];         // tree barrier

typedef unsigned long long u64;

__device__ __forceinline__ void fma2(u64 &d, u64 a, u64 b){
    asm("fma.rn.f32x2 %0, %1, %2, %0;" : "+l"(d) : "l"(a), "l"(b));
}
__device__ __forceinline__ u64 pack2(float lo, float hi){
    u64 r; asm("mov.b64 %0, {%1,%2};" : "=l"(r) : "f"(lo), "f"(hi)); return r;
}
__device__ __forceinline__ float2 unpack2(u64 v){
    float2 f; asm("mov.b64 {%0,%1}, %2;" : "=f"(f.x), "=f"(f.y) : "l"(v)); return f;
}
__device__ __forceinline__ uint32_t smem_to_u32(const void* p) {
    uint32_t a;
    asm("{ .reg .u64 t; cvta.to.shared.u64 t, %1; cvt.u32.u64 %0, t; }"
        : "=r"(a) : "l"(p));
    return a;
}
__device__ __forceinline__ void ldsm_x4(uint32_t* r, uint32_t addr){
    asm volatile("ldmatrix.sync.aligned.m8n8.x4.shared.b16 {%0,%1,%2,%3}, [%4];"
        : "=r"(r[0]),"=r"(r[1]),"=r"(r[2]),"=r"(r[3]) : "r"(addr));
}
__device__ __forceinline__ void ldsm_x2(uint32_t* r, uint32_t addr){
    asm volatile("ldmatrix.sync.aligned.m8n8.x2.shared.b16 {%0,%1}, [%2];"
        : "=r"(r[0]),"=r"(r[1]) : "r"(addr));
}
__device__ __forceinline__ void mma16816(float* c, const uint32_t* a,
                                         const uint32_t* b){
    asm volatile("mma.sync.aligned.m16n8k16.row.col.f32.bf16.bf16.f32 "
        "{%0,%1,%2,%3}, {%4,%5,%6,%7}, {%8,%9}, {%0,%1,%2,%3};"
        : "+f"(c[0]),"+f"(c[1]),"+f"(c[2]),"+f"(c[3])
        : "r"(a[0]),"r"(a[1]),"r"(a[2]),"r"(a[3]),"r"(b[0]),"r"(b[1]));
}

__device__ __forceinline__ void grid_sync(int jb, unsigned e)
{
    __syncthreads();
    if (threadIdx.x == 0) {
        __threadfence();
        atomicAdd(&g_arr[(jb & 7) * 32], 1u);
        unsigned tgt = 16u * e;
        volatile unsigned* a = g_arr;
        for (;;) {
            unsigned v0=a[0],v1=a[32],v2=a[64],v3=a[96];
            unsigned v4=a[128],v5=a[160],v6=a[192],v7=a[224];
            if (v0>=tgt&&v1>=tgt&&v2>=tgt&&v3>=tgt&&
                v4>=tgt&&v5>=tgt&&v6>=tgt&&v7>=tgt) break;
        }
        __threadfence();
    }
    __syncthreads();
}

// scan smem byte offsets
#define HPITCH    1032                    // bf16 per h/W row
#define OFF_HHI   0                       // [32][HPITCH] bf16
#define OFF_HLO   66048
#define OFF_PD    132096                  // [16 ks][32 m][36] float
#define OFF_SP    205824                  // [32 m][40] float
#define OFF_SXP   210944                  // [32 b][32 n] float
#define SMEM_BYTES (210944 + 4096)
// xproj alias (1024-thr geometry): As2 u64[16][258], Bst float[16][132]
#define XP_AP      258
#define XP_BST_OFF (16*XP_AP*2)           // float offset

extern __shared__ __align__(16) char smemc[];

__global__ void __launch_bounds__(NTHR, 1) lstm_fused(
    const float* __restrict__ A,
    const float* __restrict__ h0,
    const float* __restrict__ c0,
    const float* __restrict__ Wih,
    const float* __restrict__ bih,
    const float* __restrict__ Whh,
    const float* __restrict__ bhh,
    float* __restrict__ out)
{
    const int tid  = threadIdx.x;
    const int jb   = blockIdx.x;
    const int wid  = tid >> 5;
    const int lane = tid & 31;

    if (jb == 0 && tid < 8) { g_arr[tid*32] = 0u; __threadfence(); }
    unsigned epoch = 0;

    // ===== Phase A: xproj (proven 1024-thr fp32 f32x2), 256m x 128n =====
    {
        float* smemf = (float*)smemc;
        u64*   As2 = (u64*)smemf;
        float* Bst = smemf + XP_BST_OFF;
        const int tx   = tid & 31;
        const int ty   = tid >> 5;
        const int arow = tid >> 2;
        const int akq  = (tid & 3) * 4;

        for (int i6 = 0; i6 < 16; i6++) {
            int tt = jb*16 + i6;
            int m0 = (tt >> 5) * 256, n0 = (tt & 31) * 128;
            u64 acc[8][2];
            #pragma unroll
            for (int i = 0; i < 8; i++) { acc[i][0]=0ULL; acc[i][1]=0ULL; }
            const float* Ap = A + (size_t)(m0 + arow)*KIN + akq;
            const float* Wp = Wih + (size_t)(n0 + (arow & 127))*KIN + akq;

            for (int kc = 0; kc < KIN; kc += 16) {
                float4 av = *(const float4*)(Ap + kc);
                float4 wv;
                if (tid < 512) wv = *(const float4*)(Wp + kc);
                As2[(akq+0)*XP_AP + arow] = pack2(av.x, av.x);
                As2[(akq+1)*XP_AP + arow] = pack2(av.y, av.y);
                As2[(akq+2)*XP_AP + arow] = pack2(av.z, av.z);
                As2[(akq+3)*XP_AP + arow] = pack2(av.w, av.w);
                if (tid < 512) {
                    Bst[(akq+0)*132 + arow] = wv.x;
                    Bst[(akq+1)*132 + arow] = wv.y;
                    Bst[(akq+2)*132 + arow] = wv.z;
                    Bst[(akq+3)*132 + arow] = wv.w;
                }
                __syncthreads();
                #pragma unroll
                for (int k = 0; k < 16; k++) {
                    const ulonglong2* ap =
                        (const ulonglong2*)&As2[k*XP_AP + ty*8];
                    ulonglong2 bv = *(const ulonglong2*)&Bst[k*132 + tx*4];
                    #pragma unroll
                    for (int mh = 0; mh < 4; mh++) {
                        ulonglong2 a2 = ap[mh];
                        fma2(acc[2*mh  ][0], a2.x, bv.x);
                        fma2(acc[2*mh  ][1], a2.x, bv.y);
                        fma2(acc[2*mh+1][0], a2.y, bv.x);
                        fma2(acc[2*mh+1][1], a2.y, bv.y);
                    }
                }
                __syncthreads();
            }
            float4 bn = *(const float4*)(bih + n0 + tx*4);
            #pragma unroll
            for (int i = 0; i < 8; i++) {
                float2 v0 = unpack2(acc[i][0]), v1 = unpack2(acc[i][1]);
                float4 o;
                o.x = v0.x + bn.x; o.y = v0.y + bn.y;
                o.z = v1.x + bn.z; o.w = v1.y + bn.w;
                *(float4*)(g_xproj + (size_t)(m0 + ty*8 + i)*G_
                           + n0 + tx*4) = o;
            }
        }
    }
    grid_sync(jb, ++epoch);

    // ===== Setup: W -> bf16 hi/lo smem; h0 -> bf16 hi/lo global =====
    char* sm = smemc;
    const uint32_t smu = smem_to_u32(sm);
    __nv_bfloat16* sHhi = (__nv_bfloat16*)(sm + OFF_HHI);
    __nv_bfloat16* sHlo = (__nv_bfloat16*)(sm + OFF_HLO);
    float* pd  = (float*)(sm + OFF_PD);
    float* sp  = (float*)(sm + OFF_SP);
    float* sxp = (float*)(sm + OFF_SXP);

    for (int i = tid; i < 32*1024; i += NTHR) {
        int n = i >> 10, k = i & 1023;
        int wr = (n >> 3)*H_ + jb*8 + (n & 7);
        float v = Whh[(size_t)wr*KIN + k];
        __nv_bfloat16 hb = __float2bfloat16(v);
        sHhi[n*HPITCH + k] = hb;
        sHlo[n*HPITCH + k] = __float2bfloat16(v - __bfloat162float(hb));
    }
    if (tid < 128) {
        int u = jb*128 + tid;
        int b = u >> 9, kp = u & 511;
        float v0 = h0[b*KIN + 2*kp], v1 = h0[b*KIN + 2*kp + 1];
        __nv_bfloat16 a0 = __float2bfloat16(v0), a1 = __float2bfloat16(v1);
        __nv_bfloat162 hp; hp.x = a0; hp.y = a1;
        __nv_bfloat162 lp;
        lp.x = __float2bfloat16(v0 - __bfloat162float(a0));
        lp.y = __float2bfloat16(v1 - __bfloat162float(a1));
        g_hh[0][u] = *(unsigned*)&hp;
        g_hl[0][u] = *(unsigned*)&lp;
    }
    __syncthreads();

    // A-fragments (W): warp = (mt, ks of 16); 4 ktiles x hi/lo = 32 regs
    const int mt = wid & 1, ks = wid >> 1;      // ks 0..15, 64-wide
    uint32_t aHi[4][4], aLo[4][4];
    {
        int g = lane >> 3, r = lane & 7;
        int row = mt*16 + r + (g & 1)*8;
        int kof = (g >> 1)*8;
        #pragma unroll
        for (int kt = 0; kt < 4; kt++) {
            uint32_t boff = (uint32_t)(row*HPITCH + ks*64 + kt*16 + kof)*2;
            ldsm_x4(aHi[kt], smu + OFF_HHI + boff);
            ldsm_x4(aLo[kt], smu + OFF_HLO + boff);
        }
    }
    __syncthreads();
    grid_sync(jb, ++epoch);   // h0 conversion visible everywhere

    const int ub = tid >> 2, jjp = tid & 3;
    const int j0 = jb*8 + 2*jjp;
    float cs0 = 0.f, cs1 = 0.f;
    if (tid < 128) { cs0 = c0[ub*H_ + j0]; cs1 = c0[ub*H_ + j0 + 1]; }

    const int bl_r = lane & 7;
    const int bl_k = (lane >> 3) & 1;
    const size_t OFF_H = (size_t)B_*T_*H_;
    const size_t OFF_C = OFF_H + (size_t)B_*H_;

    // ===== Scan =====
    for (int t = 0; t < T_; t++) {
        // stage h (bf16 hi/lo) + sxp
        {
            const uint4* ph = (const uint4*)g_hh[t & 1];
            const uint4* pl = (const uint4*)g_hl[t & 1];
            #pragma unroll
            for (int it = 0; it < 4; it++) {
                int e = tid + NTHR*it;          // 0..4095
                int b = e >> 7, kq = e & 127;
                *(uint4*)(sm + OFF_HHI + (b*HPITCH + kq*8)*2) = ph[e];
                *(uint4*)(sm + OFF_HLO + (b*HPITCH + kq*8)*2) = pl[e];
            }
            {
                int v = tid;                    // 1024 threads, 1024 vals
                int b = v >> 5, n = v & 31;
                int col = (n >> 3)*H_ + jb*8 + (n & 7);
                sxp[v] = g_xproj[((size_t)b*T_ + t)*G_ + col] + bhh[col];
            }
        }
        __syncthreads();

        // MMA: 4 ktiles x 4 btiles x 3 splits
        {
            float acc[4][4];
            #pragma unroll
            for (int i = 0; i < 4; i++)
                acc[i][0]=acc[i][1]=acc[i][2]=acc[i][3]=0.f;
            #pragma unroll
            for (int kt = 0; kt < 4; kt++) {
                uint32_t k0 = (uint32_t)(ks*64 + kt*16 + bl_k*8);
                #pragma unroll
                for (int bt = 0; bt < 4; bt++) {
                    uint32_t bo = ((uint32_t)(bt*8 + bl_r)*HPITCH + k0)*2;
                    uint32_t bhi[2], blo[2];
                    ldsm_x2(bhi, smu + OFF_HHI + bo);
                    ldsm_x2(blo, smu + OFF_HLO + bo);
                    mma16816(acc[bt], aHi[kt], bhi);
                    mma16816(acc[bt], aHi[kt], blo);
                    mma16816(acc[bt], aLo[kt], bhi);
                }
            }
            int row = mt*16 + (lane >> 2);
            int bc  = (lane & 3)*2;
            #pragma unroll
            for (int bt = 0; bt < 4; bt++) {
                float* p0 = pd + (ks*32 + row)*36 + bt*8 + bc;
                p0[0] = acc[bt][0]; p0[1] = acc[bt][1];
                float* p1 = pd + (ks*32 + row + 8)*36 + bt*8 + bc;
                p1[0] = acc[bt][2]; p1[1] = acc[bt][3];
            }
        }
        __syncthreads();

        // reduce 16 k-split partials
        if (tid < 256) {
            int m = tid >> 3, q = tid & 7;
            float4 s = *(const float4*)(pd + m*36 + q*4);
            #pragma unroll
            for (int s16 = 1; s16 < 16; s16++) {
                float4 v = *(const float4*)(pd + (s16*32 + m)*36 + q*4);
                s.x += v.x; s.y += v.y; s.z += v.z; s.w += v.w;
            }
            *(float4*)(sp + m*40 + q*4) = s;
        }
        __syncthreads();

        // epilogue: thread (ub, jjp) owns cols j0, j0+1
        if (tid < 128) {
            float pre0[4], pre1[4];
            #pragma unroll
            for (int g = 0; g < 4; g++) {
                int n0 = g*8 + 2*jjp;
                pre0[g] = sp[n0*40 + ub]     + sxp[ub*32 + n0];
                pre1[g] = sp[(n0+1)*40 + ub] + sxp[ub*32 + n0 + 1];
            }
            float i0 = 1.f/(1.f+__expf(-pre0[0]));
            float f0 = 1.f/(1.f+__expf(-pre0[1]));
            float o0 = 1.f/(1.f+__expf(-pre0[2]));
            float q0 = tanhf(pre0[3]);
            float i1 = 1.f/(1.f+__expf(-pre1[0]));
            float f1 = 1.f/(1.f+__expf(-pre1[1]));
            float o1 = 1.f/(1.f+__expf(-pre1[2]));
            float q1 = tanhf(pre1[3]);
            cs0 = cs0*f0 + i0*q0;
            cs1 = cs1*f1 + i1*q1;
            float hn0 = o0 * tanhf(cs0);
            float hn1 = o1 * tanhf(cs1);

            out[((size_t)ub*T_ + t)*H_ + j0]     = hn0;
            out[((size_t)ub*T_ + t)*H_ + j0 + 1] = hn1;
            if (t == T_ - 1) {
                out[OFF_H + (size_t)ub*H_ + j0]     = hn0;
                out[OFF_H + (size_t)ub*H_ + j0 + 1] = hn1;
                out[OFF_C + (size_t)ub*H_ + j0]     = cs0;
                out[OFF_C + (size_t)ub*H_ + j0 + 1] = cs1;
            }
            __nv_bfloat16 a0 = __float2bfloat16(hn0);
            __nv_bfloat16 a1 = __float2bfloat16(hn1);
            __nv_bfloat162 hp; hp.x = a0; hp.y = a1;
            __nv_bfloat162 lp;
            lp.x = __float2bfloat16(hn0 - __bfloat162float(a0));
            lp.y = __float2bfloat16(hn1 - __bfloat162float(a1));
            g_hh[(t+1)&1][ub*512 + jb*4 + jjp] = *(unsigned*)&hp;
            g_hl[(t+1)&1][ub*512 + jb*4 + jjp] = *(unsigned*)&lp;
        }

        if (t + 1 < T_) grid_sync(jb, ++epoch);
    }
}

extern "C" void kernel_launch(void* const* d_in, const int* in_sizes, int n_in,
                              void* d_out, int out_size)
{
    (void)in_sizes; (void)n_in; (void)out_size;
    const float* inputs = (const float*)d_in[0];
    const float* h0     = (const float*)d_in[1];
    const float* c0     = (const float*)d_in[2];
    const float* Wih    = (const float*)d_in[3];
    const float* bih    = (const float*)d_in[4];
    const float* Whh    = (const float*)d_in[5];
    const float* bhh    = (const float*)d_in[6];
    float* out = (float*)d_out;

    cudaFuncSetAttribute(lstm_fused,
                         cudaFuncAttributeMaxDynamicSharedMemorySize,
                         SMEM_BYTES);

    lstm_fused<<<NBLK, NTHR, SMEM_BYTES>>>(
        inputs, h0, c0, Wih, bih, Whh, bhh, out);
}